// round 11
// baseline (speedup 1.0000x reference)
#include <cuda_runtime.h>

#define NB 2
#define NC 256
#define NL 1536
#define NH 4
#define ND 64
#define RR 50
#define NREL 101            // 2R+1
#define TT 16               // t-tile in attention kernel
#define SW (TT + 2*RR)      // 116: s-window per t-tile

// ---------------- scratch (device globals; no allocation) ----------------
__device__ float g_q  [NB*NH*NL*ND];
__device__ float g_k  [NB*NH*NL*ND];
__device__ float g_c  [NB*NH*NL*ND];
__device__ float g_ed [NB*NH*NL*NREL];
__device__ float g_att[NB*NC*NL];
__device__ float g_y  [NB*NC*NL];
__device__ float g_sum  [NC];
__device__ float g_sumsq[NC];

// ---------------- kernel 0: zero BN accumulators ----------------
__global__ void k_zero() {
    int i = threadIdx.x;
    if (i < NC) { g_sum[i] = 0.f; g_sumsq[i] = 0.f; }
}

// ---------------- kernel 1: projection GEMM ----------------
// out[o,(b,l)] = sum_c W[o,c] * x[b,c,l] + bias[o]
// stored transposed: outT[b,h,l,d] with o = h*64+d  (contiguous d)
// which: 0 -> g_c, 1 -> g_q, 2 -> g_k
__global__ void __launch_bounds__(256) k_proj(
    const float* __restrict__ W, const float* __restrict__ bias,
    const float* __restrict__ x, int which)
{
    __shared__ float sA[16][65];   // W^T tile  [k][m]
    __shared__ float sB[16][68];   // x tile    [k][j]  (pad 68 keeps float4 align)

    const int l0 = blockIdx.x * 64;
    const int o0 = blockIdx.y * 64;
    const int b  = blockIdx.z;
    const int tid = threadIdx.x;
    const int tx = tid & 15, ty = tid >> 4;
    const int m0 = ty * 4,  j0 = tx * 4;
    const int am = tid >> 2, ak = (tid & 3) * 4;
    const int bk = tid >> 4, bj = (tid & 15) * 4;
    const float* xb = x + b * NC * NL;

    float acc[4][4] = {};
    for (int c0 = 0; c0 < NC; c0 += 16) {
        float4 a4 = *(const float4*)(W + (o0 + am) * NC + c0 + ak);
        sA[ak+0][am] = a4.x; sA[ak+1][am] = a4.y;
        sA[ak+2][am] = a4.z; sA[ak+3][am] = a4.w;
        *(float4*)&sB[bk][bj] = *(const float4*)(xb + (c0 + bk) * NL + l0 + bj);
        __syncthreads();
        #pragma unroll
        for (int k = 0; k < 16; k++) {
            float a0 = sA[k][m0+0], a1 = sA[k][m0+1];
            float a2 = sA[k][m0+2], a3 = sA[k][m0+3];
            float4 bb = *(const float4*)&sB[k][j0];
            acc[0][0] += a0*bb.x; acc[0][1] += a0*bb.y; acc[0][2] += a0*bb.z; acc[0][3] += a0*bb.w;
            acc[1][0] += a1*bb.x; acc[1][1] += a1*bb.y; acc[1][2] += a1*bb.z; acc[1][3] += a1*bb.w;
            acc[2][0] += a2*bb.x; acc[2][1] += a2*bb.y; acc[2][2] += a2*bb.z; acc[2][3] += a2*bb.w;
            acc[3][0] += a3*bb.x; acc[3][1] += a3*bb.y; acc[3][2] += a3*bb.z; acc[3][3] += a3*bb.w;
        }
        __syncthreads();
    }
    float* outT = (which == 0) ? g_c : (which == 1) ? g_q : g_k;
    #pragma unroll
    for (int i = 0; i < 4; i++) {
        int o = o0 + m0 + i;
        float bv = bias[o];
        int h = o >> 6, d = o & 63;
        float* dst = outT + (size_t)((b*NH + h)*NL) * ND + d;
        #pragma unroll
        for (int j = 0; j < 4; j++) {
            int l = l0 + j0 + j;
            dst[(size_t)l * ND] = acc[i][j] + bv;
        }
    }
}

// ---------------- kernel 2: relative-position dot  g_ed = 0.3 * q . emb ----------------
// grid (NL/32, NH, NB), 256 threads
__global__ void __launch_bounds__(256) k_ed(const float* __restrict__ emb)
{
    __shared__ float sQ[32][65];
    __shared__ float sE[NREL][65];
    const int t0 = blockIdx.x * 32;
    const int bh = blockIdx.z * NH + blockIdx.y;
    const int tid = threadIdx.x;

    const float* qb = g_q + (size_t)(bh*NL + t0) * ND;
    for (int i = tid; i < 32*64; i += 256) sQ[i >> 6][i & 63] = qb[i];
    for (int i = tid; i < NREL*64; i += 256) sE[i >> 6][i & 63] = emb[i];
    __syncthreads();

    float* ed = g_ed + (size_t)(bh*NL + t0) * NREL;
    for (int idx = tid; idx < 32*NREL; idx += 256) {
        int tt = idx / NREL, r = idx - tt * NREL;
        float a = 0.f;
        #pragma unroll
        for (int d = 0; d < 64; d++) a += sQ[tt][d] * sE[r][d];
        ed[tt*NREL + r] = 0.3f * a;
    }
}

// ---------------- kernel 3: banded attention ----------------
// grid (NL/TT, NH, NB), 256 threads. ~48KB static smem.
__global__ void __launch_bounds__(256) k_attn(const float* __restrict__ emb)
{
    __shared__ float sQ [TT][65];
    __shared__ float sKC[SW][65];      // K first, then reused for content
    __shared__ float sS [TT][SW + 1];  // scores -> softmax weights
    __shared__ float sEd[TT][NREL];

    const int t0 = blockIdx.x * TT;
    const int bh = blockIdx.z * NH + blockIdx.y;
    const int tid = threadIdx.x;
    const int s0 = t0 - RR;

    const float* qb = g_q + (size_t)(bh*NL + t0) * ND;
    for (int i = tid; i < TT*64; i += 256) sQ[i >> 6][i & 63] = qb[i];
    const float* kb = g_k + (size_t)bh * NL * ND;
    for (int i = tid; i < SW*64; i += 256) {
        int j = i >> 6, d = i & 63;
        int s = s0 + j;
        sKC[j][d] = (s >= 0 && s < NL) ? kb[(size_t)s*ND + d] : 0.f;
    }
    const float* edb = g_ed + (size_t)(bh*NL + t0) * NREL;
    for (int i = tid; i < TT*NREL; i += 256) sEd[i / NREL][i % NREL] = edb[i];
    __syncthreads();

    // scores: S[tt][j] = q[t].k[s] + ed[tt][ridx], band-masked
    for (int idx = tid; idx < TT*SW; idx += 256) {
        int tt = idx / SW, j = idx - tt * SW;
        int s = s0 + j;
        float v = -1e30f;
        if (s >= 0 && s < NL && j >= tt && j <= tt + 2*RR) {
            float a = 0.f;
            #pragma unroll
            for (int d = 0; d < 64; d++) a += sQ[tt][d] * sKC[j][d];
            v = a + sEd[tt][tt + 2*RR - j];
        }
        sS[tt][j] = v;
    }
    __syncthreads();

    // overwrite K with content (no reader of sKC between these barriers)
    const float* cb = g_c + (size_t)bh * NL * ND;
    for (int i = tid; i < SW*64; i += 256) {
        int j = i >> 6, d = i & 63;
        int s = s0 + j;
        sKC[j][d] = (s >= 0 && s < NL) ? cb[(size_t)s*ND + d] : 0.f;
    }

    // softmax: each warp owns 2 rows (exclusive sS rows -> no race)
    {
        int w = tid >> 5, lane = tid & 31;
        for (int tt = w; tt < TT; tt += 8) {
            float m = -1e30f;
            for (int j = lane; j < SW; j += 32) m = fmaxf(m, sS[tt][j]);
            #pragma unroll
            for (int o = 16; o; o >>= 1) m = fmaxf(m, __shfl_xor_sync(0xffffffffu, m, o));
            float sum = 0.f;
            for (int j = lane; j < SW; j += 32) {
                float e = __expf(sS[tt][j] - m);
                sS[tt][j] = e;
                sum += e;
            }
            #pragma unroll
            for (int o = 16; o; o >>= 1) sum += __shfl_xor_sync(0xffffffffu, sum, o);
            float inv = 1.f / sum;
            for (int j = lane; j < SW; j += 32) sS[tt][j] *= inv;
        }
    }
    __syncthreads();

    // output: only j in [tt, tt+2R] can have w != 0, and there ridx = 2R - jj
    float* ob = g_att + (size_t)blockIdx.z * NC * NL + (size_t)blockIdx.y * 64 * NL;
    for (int idx = tid; idx < TT*64; idx += 256) {
        int tt = idx >> 6, c = idx & 63;
        float acc = 0.f;
        #pragma unroll 4
        for (int jj = 0; jj < NREL; jj++) {
            int j = tt + jj;
            float w = sS[tt][j];
            acc += w * (sKC[j][c] + 0.3f * __ldg(&emb[(2*RR - jj) * 64 + c]));
        }
        ob[(size_t)c * NL + t0 + tt] = acc;
    }
}

// ---------------- kernel 4: final projection Wf + bias, fused BN stats ----------------
__global__ void __launch_bounds__(256) k_final(
    const float* __restrict__ W, const float* __restrict__ bias)
{
    __shared__ float sA[16][65];
    __shared__ float sB[16][68];

    const int l0 = blockIdx.x * 64;
    const int o0 = blockIdx.y * 64;
    const int b  = blockIdx.z;
    const int tid = threadIdx.x;
    const int tx = tid & 15, ty = tid >> 4;
    const int m0 = ty * 4,  j0 = tx * 4;
    const int am = tid >> 2, ak = (tid & 3) * 4;
    const int bk = tid >> 4, bj = (tid & 15) * 4;
    const float* xb = g_att + (size_t)b * NC * NL;

    float acc[4][4] = {};
    for (int c0 = 0; c0 < NC; c0 += 16) {
        float4 a4 = *(const float4*)(W + (o0 + am) * NC + c0 + ak);
        sA[ak+0][am] = a4.x; sA[ak+1][am] = a4.y;
        sA[ak+2][am] = a4.z; sA[ak+3][am] = a4.w;
        *(float4*)&sB[bk][bj] = *(const float4*)(xb + (c0 + bk) * NL + l0 + bj);
        __syncthreads();
        #pragma unroll
        for (int k = 0; k < 16; k++) {
            float a0 = sA[k][m0+0], a1 = sA[k][m0+1];
            float a2 = sA[k][m0+2], a3 = sA[k][m0+3];
            float4 bb = *(const float4*)&sB[k][j0];
            acc[0][0] += a0*bb.x; acc[0][1] += a0*bb.y; acc[0][2] += a0*bb.z; acc[0][3] += a0*bb.w;
            acc[1][0] += a1*bb.x; acc[1][1] += a1*bb.y; acc[1][2] += a1*bb.z; acc[1][3] += a1*bb.w;
            acc[2][0] += a2*bb.x; acc[2][1] += a2*bb.y; acc[2][2] += a2*bb.z; acc[2][3] += a2*bb.w;
            acc[3][0] += a3*bb.x; acc[3][1] += a3*bb.y; acc[3][2] += a3*bb.z; acc[3][3] += a3*bb.w;
        }
        __syncthreads();
    }

    float* yb = g_y + (size_t)b * NC * NL;
    #pragma unroll
    for (int i = 0; i < 4; i++) {
        int o = o0 + m0 + i;
        float bv = bias[o];
        float s1 = 0.f, s2 = 0.f;
        #pragma unroll
        for (int j = 0; j < 4; j++) {
            float v = acc[i][j] + bv;
            yb[(size_t)o * NL + l0 + j0 + j] = v;
            s1 += v; s2 += v * v;
        }
        // reduce across the 16 tx lanes (xor <= 8 stays within each 16-lane half)
        #pragma unroll
        for (int off = 8; off; off >>= 1) {
            s1 += __shfl_xor_sync(0xffffffffu, s1, off);
            s2 += __shfl_xor_sync(0xffffffffu, s2, off);
        }
        if (tx == 0) {
            atomicAdd(&g_sum[o],   s1);
            atomicAdd(&g_sumsq[o], s2);
        }
    }
}

// ---------------- kernel 5: BN finalize + ReLU + scale ----------------
__global__ void __launch_bounds__(256) k_bn(
    const float* __restrict__ gamma, const float* __restrict__ beta,
    const float* __restrict__ scale, float* __restrict__ out)
{
    int idx = blockIdx.x * 256 + threadIdx.x;
    if (idx >= NB*NC*NL) return;
    int ch = (idx / NL) & (NC - 1);
    const float invN = 1.f / (float)(NB * NL);
    float mean = g_sum[ch] * invN;
    float var  = g_sumsq[ch] * invN - mean * mean;
    float v = (g_y[idx] - mean) * rsqrtf(var + 1e-5f) * gamma[ch] + beta[ch];
    out[idx] = fmaxf(v, 0.f) * scale[ch];
}

// ---------------- launch ----------------
extern "C" void kernel_launch(void* const* d_in, const int* in_sizes, int n_in,
                              void* d_out, int out_size)
{
    const float* x     = (const float*)d_in[0];
    const float* Wc    = (const float*)d_in[1];
    const float* bc    = (const float*)d_in[2];
    const float* Wq    = (const float*)d_in[3];
    const float* bq    = (const float*)d_in[4];
    const float* Wk    = (const float*)d_in[5];
    const float* bk    = (const float*)d_in[6];
    const float* emb   = (const float*)d_in[7];
    const float* Wf    = (const float*)d_in[8];
    const float* bf    = (const float*)d_in[9];
    const float* gamma = (const float*)d_in[10];
    const float* beta  = (const float*)d_in[11];
    const float* scale = (const float*)d_in[12];
    float* out = (float*)d_out;

    k_zero<<<1, 256>>>();

    dim3 gG(NL/64, NC/64, NB);
    k_proj<<<gG, 256>>>(Wc, bc, x, 0);
    k_proj<<<gG, 256>>>(Wq, bq, x, 1);
    k_proj<<<gG, 256>>>(Wk, bk, x, 2);

    dim3 gE(NL/32, NH, NB);
    k_ed<<<gE, 256>>>(emb);

    dim3 gA(NL/TT, NH, NB);
    k_attn<<<gA, 256>>>(emb);

    k_final<<<gG, 256>>>(Wf, bf);

    int total = NB*NC*NL;
    k_bn<<<(total + 255)/256, 256>>>(gamma, beta, scale, out);
}

// round 12
// speedup vs baseline: 1.0002x; 1.0002x over previous
#include <cuda_runtime.h>

#define NB 2
#define NC 256
#define NL 1536
#define NH 4
#define ND 64
#define RR 50
#define NREL 101            // 2R+1
#define TT 16               // t-tile in attention kernel
#define SW (TT + 2*RR)      // 116: s-window per t-tile

// ---------------- scratch (device globals; no allocation) ----------------
__device__ float g_q  [NB*NH*NL*ND];
__device__ float g_k  [NB*NH*NL*ND];
__device__ float g_c  [NB*NH*NL*ND];
__device__ float g_ed [NB*NH*NL*NREL];
__device__ float g_att[NB*NC*NL];
__device__ float g_y  [NB*NC*NL];
__device__ float g_sum  [NC];
__device__ float g_sumsq[NC];

// ---------------- kernel 0: zero BN accumulators ----------------
__global__ void k_zero() {
    int i = threadIdx.x;
    if (i < NC) { g_sum[i] = 0.f; g_sumsq[i] = 0.f; }
}

// ---------------- kernel 1: projection GEMM ----------------
// out[o,(b,l)] = sum_c W[o,c] * x[b,c,l] + bias[o]
// stored transposed: outT[b,h,l,d] with o = h*64+d  (contiguous d)
// which: 0 -> g_c, 1 -> g_q, 2 -> g_k
__global__ void __launch_bounds__(256) k_proj(
    const float* __restrict__ W, const float* __restrict__ bias,
    const float* __restrict__ x, int which)
{
    __shared__ float sA[16][65];   // W^T tile  [k][m]
    __shared__ float sB[16][68];   // x tile    [k][j]  (pad 68 keeps float4 align)

    const int l0 = blockIdx.x * 64;
    const int o0 = blockIdx.y * 64;
    const int b  = blockIdx.z;
    const int tid = threadIdx.x;
    const int tx = tid & 15, ty = tid >> 4;
    const int m0 = ty * 4,  j0 = tx * 4;
    const int am = tid >> 2, ak = (tid & 3) * 4;
    const int bk = tid >> 4, bj = (tid & 15) * 4;
    const float* xb = x + b * NC * NL;

    float acc[4][4] = {};
    for (int c0 = 0; c0 < NC; c0 += 16) {
        float4 a4 = *(const float4*)(W + (o0 + am) * NC + c0 + ak);
        sA[ak+0][am] = a4.x; sA[ak+1][am] = a4.y;
        sA[ak+2][am] = a4.z; sA[ak+3][am] = a4.w;
        *(float4*)&sB[bk][bj] = *(const float4*)(xb + (c0 + bk) * NL + l0 + bj);
        __syncthreads();
        #pragma unroll
        for (int k = 0; k < 16; k++) {
            float a0 = sA[k][m0+0], a1 = sA[k][m0+1];
            float a2 = sA[k][m0+2], a3 = sA[k][m0+3];
            float4 bb = *(const float4*)&sB[k][j0];
            acc[0][0] += a0*bb.x; acc[0][1] += a0*bb.y; acc[0][2] += a0*bb.z; acc[0][3] += a0*bb.w;
            acc[1][0] += a1*bb.x; acc[1][1] += a1*bb.y; acc[1][2] += a1*bb.z; acc[1][3] += a1*bb.w;
            acc[2][0] += a2*bb.x; acc[2][1] += a2*bb.y; acc[2][2] += a2*bb.z; acc[2][3] += a2*bb.w;
            acc[3][0] += a3*bb.x; acc[3][1] += a3*bb.y; acc[3][2] += a3*bb.z; acc[3][3] += a3*bb.w;
        }
        __syncthreads();
    }
    float* outT = (which == 0) ? g_c : (which == 1) ? g_q : g_k;
    #pragma unroll
    for (int i = 0; i < 4; i++) {
        int o = o0 + m0 + i;
        float bv = bias[o];
        int h = o >> 6, d = o & 63;
        float* dst = outT + (size_t)((b*NH + h)*NL) * ND + d;
        #pragma unroll
        for (int j = 0; j < 4; j++) {
            int l = l0 + j0 + j;
            dst[(size_t)l * ND] = acc[i][j] + bv;
        }
    }
}

// ---------------- kernel 2: relative-position dot  g_ed = 0.3 * q . emb ----------------
// grid (NL/32, NH, NB), 256 threads
__global__ void __launch_bounds__(256) k_ed(const float* __restrict__ emb)
{
    __shared__ float sQ[32][65];
    __shared__ float sE[NREL][65];
    const int t0 = blockIdx.x * 32;
    const int bh = blockIdx.z * NH + blockIdx.y;
    const int tid = threadIdx.x;

    const float* qb = g_q + (size_t)(bh*NL + t0) * ND;
    for (int i = tid; i < 32*64; i += 256) sQ[i >> 6][i & 63] = qb[i];
    for (int i = tid; i < NREL*64; i += 256) sE[i >> 6][i & 63] = emb[i];
    __syncthreads();

    float* ed = g_ed + (size_t)(bh*NL + t0) * NREL;
    for (int idx = tid; idx < 32*NREL; idx += 256) {
        int tt = idx / NREL, r = idx - tt * NREL;
        float a = 0.f;
        #pragma unroll
        for (int d = 0; d < 64; d++) a += sQ[tt][d] * sE[r][d];
        ed[tt*NREL + r] = 0.3f * a;
    }
}

// ---------------- kernel 3: banded attention ----------------
// grid (NL/TT, NH, NB), 256 threads. ~48KB static smem.
__global__ void __launch_bounds__(256) k_attn(const float* __restrict__ emb)
{
    __shared__ float sQ [TT][65];
    __shared__ float sKC[SW][65];      // K first, then reused for content
    __shared__ float sS [TT][SW + 1];  // scores -> softmax weights
    __shared__ float sEd[TT][NREL];

    const int t0 = blockIdx.x * TT;
    const int bh = blockIdx.z * NH + blockIdx.y;
    const int tid = threadIdx.x;
    const int s0 = t0 - RR;

    const float* qb = g_q + (size_t)(bh*NL + t0) * ND;
    for (int i = tid; i < TT*64; i += 256) sQ[i >> 6][i & 63] = qb[i];
    const float* kb = g_k + (size_t)bh * NL * ND;
    for (int i = tid; i < SW*64; i += 256) {
        int j = i >> 6, d = i & 63;
        int s = s0 + j;
        sKC[j][d] = (s >= 0 && s < NL) ? kb[(size_t)s*ND + d] : 0.f;
    }
    const float* edb = g_ed + (size_t)(bh*NL + t0) * NREL;
    for (int i = tid; i < TT*NREL; i += 256) sEd[i / NREL][i % NREL] = edb[i];
    __syncthreads();

    // scores: S[tt][j] = q[t].k[s] + ed[tt][ridx], band-masked
    for (int idx = tid; idx < TT*SW; idx += 256) {
        int tt = idx / SW, j = idx - tt * SW;
        int s = s0 + j;
        float v = -1e30f;
        if (s >= 0 && s < NL && j >= tt && j <= tt + 2*RR) {
            float a = 0.f;
            #pragma unroll
            for (int d = 0; d < 64; d++) a += sQ[tt][d] * sKC[j][d];
            v = a + sEd[tt][tt + 2*RR - j];
        }
        sS[tt][j] = v;
    }
    __syncthreads();

    // overwrite K with content (no reader of sKC between these barriers)
    const float* cb = g_c + (size_t)bh * NL * ND;
    for (int i = tid; i < SW*64; i += 256) {
        int j = i >> 6, d = i & 63;
        int s = s0 + j;
        sKC[j][d] = (s >= 0 && s < NL) ? cb[(size_t)s*ND + d] : 0.f;
    }

    // softmax: each warp owns 2 rows (exclusive sS rows -> no race)
    {
        int w = tid >> 5, lane = tid & 31;
        for (int tt = w; tt < TT; tt += 8) {
            float m = -1e30f;
            for (int j = lane; j < SW; j += 32) m = fmaxf(m, sS[tt][j]);
            #pragma unroll
            for (int o = 16; o; o >>= 1) m = fmaxf(m, __shfl_xor_sync(0xffffffffu, m, o));
            float sum = 0.f;
            for (int j = lane; j < SW; j += 32) {
                float e = __expf(sS[tt][j] - m);
                sS[tt][j] = e;
                sum += e;
            }
            #pragma unroll
            for (int o = 16; o; o >>= 1) sum += __shfl_xor_sync(0xffffffffu, sum, o);
            float inv = 1.f / sum;
            for (int j = lane; j < SW; j += 32) sS[tt][j] *= inv;
        }
    }
    __syncthreads();

    // output: only j in [tt, tt+2R] can have w != 0, and there ridx = 2R - jj
    float* ob = g_att + (size_t)blockIdx.z * NC * NL + (size_t)blockIdx.y * 64 * NL;
    for (int idx = tid; idx < TT*64; idx += 256) {
        int tt = idx >> 6, c = idx & 63;
        float acc = 0.f;
        #pragma unroll 4
        for (int jj = 0; jj < NREL; jj++) {
            int j = tt + jj;
            float w = sS[tt][j];
            acc += w * (sKC[j][c] + 0.3f * __ldg(&emb[(2*RR - jj) * 64 + c]));
        }
        ob[(size_t)c * NL + t0 + tt] = acc;
    }
}

// ---------------- kernel 4: final projection Wf + bias, fused BN stats ----------------
__global__ void __launch_bounds__(256) k_final(
    const float* __restrict__ W, const float* __restrict__ bias)
{
    __shared__ float sA[16][65];
    __shared__ float sB[16][68];

    const int l0 = blockIdx.x * 64;
    const int o0 = blockIdx.y * 64;
    const int b  = blockIdx.z;
    const int tid = threadIdx.x;
    const int tx = tid & 15, ty = tid >> 4;
    const int m0 = ty * 4,  j0 = tx * 4;
    const int am = tid >> 2, ak = (tid & 3) * 4;
    const int bk = tid >> 4, bj = (tid & 15) * 4;
    const float* xb = g_att + (size_t)b * NC * NL;

    float acc[4][4] = {};
    for (int c0 = 0; c0 < NC; c0 += 16) {
        float4 a4 = *(const float4*)(W + (o0 + am) * NC + c0 + ak);
        sA[ak+0][am] = a4.x; sA[ak+1][am] = a4.y;
        sA[ak+2][am] = a4.z; sA[ak+3][am] = a4.w;
        *(float4*)&sB[bk][bj] = *(const float4*)(xb + (c0 + bk) * NL + l0 + bj);
        __syncthreads();
        #pragma unroll
        for (int k = 0; k < 16; k++) {
            float a0 = sA[k][m0+0], a1 = sA[k][m0+1];
            float a2 = sA[k][m0+2], a3 = sA[k][m0+3];
            float4 bb = *(const float4*)&sB[k][j0];
            acc[0][0] += a0*bb.x; acc[0][1] += a0*bb.y; acc[0][2] += a0*bb.z; acc[0][3] += a0*bb.w;
            acc[1][0] += a1*bb.x; acc[1][1] += a1*bb.y; acc[1][2] += a1*bb.z; acc[1][3] += a1*bb.w;
            acc[2][0] += a2*bb.x; acc[2][1] += a2*bb.y; acc[2][2] += a2*bb.z; acc[2][3] += a2*bb.w;
            acc[3][0] += a3*bb.x; acc[3][1] += a3*bb.y; acc[3][2] += a3*bb.z; acc[3][3] += a3*bb.w;
        }
        __syncthreads();
    }

    float* yb = g_y + (size_t)b * NC * NL;
    #pragma unroll
    for (int i = 0; i < 4; i++) {
        int o = o0 + m0 + i;
        float bv = bias[o];
        float s1 = 0.f, s2 = 0.f;
        #pragma unroll
        for (int j = 0; j < 4; j++) {
            float v = acc[i][j] + bv;
            yb[(size_t)o * NL + l0 + j0 + j] = v;
            s1 += v; s2 += v * v;
        }
        // reduce across the 16 tx lanes (xor <= 8 stays within each 16-lane half)
        #pragma unroll
        for (int off = 8; off; off >>= 1) {
            s1 += __shfl_xor_sync(0xffffffffu, s1, off);
            s2 += __shfl_xor_sync(0xffffffffu, s2, off);
        }
        if (tx == 0) {
            atomicAdd(&g_sum[o],   s1);
            atomicAdd(&g_sumsq[o], s2);
        }
    }
}

// ---------------- kernel 5: BN finalize + ReLU + scale ----------------
__global__ void __launch_bounds__(256) k_bn(
    const float* __restrict__ gamma, const float* __restrict__ beta,
    const float* __restrict__ scale, float* __restrict__ out)
{
    int idx = blockIdx.x * 256 + threadIdx.x;
    if (idx >= NB*NC*NL) return;
    int ch = (idx / NL) & (NC - 1);
    const float invN = 1.f / (float)(NB * NL);
    float mean = g_sum[ch] * invN;
    float var  = g_sumsq[ch] * invN - mean * mean;
    float v = (g_y[idx] - mean) * rsqrtf(var + 1e-5f) * gamma[ch] + beta[ch];
    out[idx] = fmaxf(v, 0.f) * scale[ch];
}

// ---------------- launch ----------------
extern "C" void kernel_launch(void* const* d_in, const int* in_sizes, int n_in,
                              void* d_out, int out_size)
{
    const float* x     = (const float*)d_in[0];
    const float* Wc    = (const float*)d_in[1];
    const float* bc    = (const float*)d_in[2];
    const float* Wq    = (const float*)d_in[3];
    const float* bq    = (const float*)d_in[4];
    const float* Wk    = (const float*)d_in[5];
    const float* bk    = (const float*)d_in[6];
    const float* emb   = (const float*)d_in[7];
    const float* Wf    = (const float*)d_in[8];
    const float* bf    = (const float*)d_in[9];
    const float* gamma = (const float*)d_in[10];
    const float* beta  = (const float*)d_in[11];
    const float* scale = (const float*)d_in[12];
    float* out = (float*)d_out;

    k_zero<<<1, 256>>>();

    dim3 gG(NL/64, NC/64, NB);
    k_proj<<<gG, 256>>>(Wc, bc, x, 0);
    k_proj<<<gG, 256>>>(Wq, bq, x, 1);
    k_proj<<<gG, 256>>>(Wk, bk, x, 2);

    dim3 gE(NL/32, NH, NB);
    k_ed<<<gE, 256>>>(emb);

    dim3 gA(NL/TT, NH, NB);
    k_attn<<<gA, 256>>>(emb);

    k_final<<<gG, 256>>>(Wf, bf);

    int total = NB*NC*NL;
    k_bn<<<(total + 255)/256, 256>>>(gamma, beta, scale, out);
}

// round 13
// speedup vs baseline: 1.3483x; 1.3480x over previous
#include <cuda_runtime.h>

#define NB 2
#define NC 256
#define NL 1536
#define NH 4
#define ND 64
#define RR 50
#define NREL 101            // 2R+1
#define TT 16               // t-tile in attention kernel
#define SW (TT + 2*RR)      // 116: s-window per t-tile

// ---------------- scratch (device globals; no allocation) ----------------
__device__ float g_q  [NB*NH*NL*ND];
__device__ float g_k  [NB*NH*NL*ND];
__device__ float g_c  [NB*NH*NL*ND];
__device__ float g_att[NB*NC*NL];
__device__ float g_y  [NB*NC*NL];
__device__ float g_sum  [NC];
__device__ float g_sumsq[NC];

// ---------------- kernel 0: zero BN accumulators ----------------
__global__ void k_zero() {
    int i = threadIdx.x;
    if (i < NC) { g_sum[i] = 0.f; g_sumsq[i] = 0.f; }
}

// ---------------- kernel 1: fused projection GEMMs (Wc, Wq, Wk in one grid) ----------------
// out[o,(b,l)] = sum_c W[o,c] * x[b,c,l] + bias[o]
// stored transposed: outT[b,h,l,d] with o = h*64+d  (contiguous d)
// blockIdx.y in [0,12): wsel = y>>2 selects matrix, o0 = (y&3)*64
__global__ void __launch_bounds__(256) k_proj3(
    const float* __restrict__ Wc, const float* __restrict__ bc,
    const float* __restrict__ Wq, const float* __restrict__ bq,
    const float* __restrict__ Wk, const float* __restrict__ bk,
    const float* __restrict__ x)
{
    __shared__ float sA[16][68];   // W^T tile [k][m], 68-pad -> 272B rows, float4-aligned
    __shared__ float sB[16][68];   // x tile   [k][j]

    const int l0 = blockIdx.x * 64;
    const int wsel = blockIdx.y >> 2;
    const int o0 = (blockIdx.y & 3) * 64;
    const int b  = blockIdx.z;
    const int tid = threadIdx.x;
    const int tx = tid & 15, ty = tid >> 4;
    const int m0 = ty * 4,  j0 = tx * 4;
    const int am = tid >> 2, ak = (tid & 3) * 4;
    const int bk2 = tid >> 4, bj = (tid & 15) * 4;

    const float* W    = (wsel == 0) ? Wc : (wsel == 1) ? Wq : Wk;
    const float* bias = (wsel == 0) ? bc : (wsel == 1) ? bq : bk;
    float* outT       = (wsel == 0) ? g_c : (wsel == 1) ? g_q : g_k;
    const float* xb = x + b * NC * NL;

    float acc[4][4] = {};
    for (int c0 = 0; c0 < NC; c0 += 16) {
        float4 a4 = *(const float4*)(W + (o0 + am) * NC + c0 + ak);
        sA[ak+0][am] = a4.x; sA[ak+1][am] = a4.y;
        sA[ak+2][am] = a4.z; sA[ak+3][am] = a4.w;
        *(float4*)&sB[bk2][bj] = *(const float4*)(xb + (c0 + bk2) * NL + l0 + bj);
        __syncthreads();
        #pragma unroll
        for (int k = 0; k < 16; k++) {
            float4 av = *(const float4*)&sA[k][m0];
            float4 bv = *(const float4*)&sB[k][j0];
            acc[0][0] += av.x*bv.x; acc[0][1] += av.x*bv.y; acc[0][2] += av.x*bv.z; acc[0][3] += av.x*bv.w;
            acc[1][0] += av.y*bv.x; acc[1][1] += av.y*bv.y; acc[1][2] += av.y*bv.z; acc[1][3] += av.y*bv.w;
            acc[2][0] += av.z*bv.x; acc[2][1] += av.z*bv.y; acc[2][2] += av.z*bv.z; acc[2][3] += av.z*bv.w;
            acc[3][0] += av.w*bv.x; acc[3][1] += av.w*bv.y; acc[3][2] += av.w*bv.z; acc[3][3] += av.w*bv.w;
        }
        __syncthreads();
    }
    #pragma unroll
    for (int i = 0; i < 4; i++) {
        int o = o0 + m0 + i;
        float bv = bias[o];
        int h = o >> 6, d = o & 63;
        float* dst = outT + (size_t)((b*NH + h)*NL) * ND + d;
        #pragma unroll
        for (int j = 0; j < 4; j++) {
            int l = l0 + j0 + j;
            dst[(size_t)l * ND] = acc[i][j] + bv;
        }
    }
}

// ---------------- kernel 2: banded attention (rel-emb dot fused in) ----------------
// grid (NL/TT, NH, NB), 256 threads, ~66.5KB dynamic smem.
__global__ void __launch_bounds__(256) k_attn(const float* __restrict__ emb)
{
    extern __shared__ float smem[];
    float (*sQ  )[65]   = (float(*)[65]  )(smem);                       // 16 x 65
    float (*sKC )[65]   = (float(*)[65]  )(smem + TT*65);               // 116 x 65
    float (*sS  )[SW+1] = (float(*)[SW+1])(smem + TT*65 + SW*65);       // 16 x 117
    float (*sEmb)[65]   = (float(*)[65]  )(smem + TT*65 + SW*65 + TT*(SW+1)); // 101 x 65

    const int t0 = blockIdx.x * TT;
    const int bh = blockIdx.z * NH + blockIdx.y;
    const int tid = threadIdx.x;
    const int s0 = t0 - RR;

    const float* qb = g_q + (size_t)(bh*NL + t0) * ND;
    for (int i = tid; i < TT*64; i += 256) sQ[i >> 6][i & 63] = qb[i];
    const float* kb = g_k + (size_t)bh * NL * ND;
    for (int i = tid; i < SW*64; i += 256) {
        int j = i >> 6, d = i & 63;
        int s = s0 + j;
        sKC[j][d] = (s >= 0 && s < NL) ? kb[(size_t)s*ND + d] : 0.f;
    }
    for (int i = tid; i < NREL*64; i += 256) sEmb[i >> 6][i & 63] = 0.3f * emb[i];
    __syncthreads();

    // scores: S[tt][j] = q[t].(k[s] + 0.3*emb[r]),  r = tt + 2R - j, band-masked
    for (int idx = tid; idx < TT*SW; idx += 256) {
        int tt = idx / SW, j = idx - tt * SW;
        int s = s0 + j;
        float v = -1e30f;
        if (s >= 0 && s < NL && j >= tt && j <= tt + 2*RR) {
            int r = tt + 2*RR - j;
            float a = 0.f;
            #pragma unroll
            for (int d = 0; d < 64; d++) a += sQ[tt][d] * (sKC[j][d] + sEmb[r][d]);
            v = a;
        }
        sS[tt][j] = v;
    }
    __syncthreads();

    // overwrite K with content (no reader of sKC between these barriers)
    const float* cb = g_c + (size_t)bh * NL * ND;
    for (int i = tid; i < SW*64; i += 256) {
        int j = i >> 6, d = i & 63;
        int s = s0 + j;
        sKC[j][d] = (s >= 0 && s < NL) ? cb[(size_t)s*ND + d] : 0.f;
    }

    // softmax: each warp owns rows (exclusive sS rows -> no race)
    {
        int w = tid >> 5, lane = tid & 31;
        for (int tt = w; tt < TT; tt += 8) {
            float m = -1e30f;
            for (int j = lane; j < SW; j += 32) m = fmaxf(m, sS[tt][j]);
            #pragma unroll
            for (int o = 16; o; o >>= 1) m = fmaxf(m, __shfl_xor_sync(0xffffffffu, m, o));
            float sum = 0.f;
            for (int j = lane; j < SW; j += 32) {
                float e = __expf(sS[tt][j] - m);
                sS[tt][j] = e;
                sum += e;
            }
            #pragma unroll
            for (int o = 16; o; o >>= 1) sum += __shfl_xor_sync(0xffffffffu, sum, o);
            float inv = 1.f / sum;
            for (int j = lane; j < SW; j += 32) sS[tt][j] *= inv;
        }
    }
    __syncthreads();

    // output: only j in [tt, tt+2R] can have w != 0, and there r = 2R - jj
    float* ob = g_att + (size_t)blockIdx.z * NC * NL + (size_t)blockIdx.y * 64 * NL;
    for (int idx = tid; idx < TT*64; idx += 256) {
        int tt = idx >> 6, c = idx & 63;
        float acc = 0.f;
        #pragma unroll 4
        for (int jj = 0; jj < NREL; jj++) {
            int j = tt + jj;
            float w = sS[tt][j];
            acc += w * (sKC[j][c] + sEmb[2*RR - jj][c]);
        }
        ob[(size_t)c * NL + t0 + tt] = acc;
    }
}

// ---------------- kernel 3: final projection Wf + bias, fused BN stats ----------------
__global__ void __launch_bounds__(256) k_final(
    const float* __restrict__ W, const float* __restrict__ bias)
{
    __shared__ float sA[16][68];
    __shared__ float sB[16][68];

    const int l0 = blockIdx.x * 64;
    const int o0 = blockIdx.y * 64;
    const int b  = blockIdx.z;
    const int tid = threadIdx.x;
    const int tx = tid & 15, ty = tid >> 4;
    const int m0 = ty * 4,  j0 = tx * 4;
    const int am = tid >> 2, ak = (tid & 3) * 4;
    const int bk2 = tid >> 4, bj = (tid & 15) * 4;
    const float* xb = g_att + (size_t)b * NC * NL;

    float acc[4][4] = {};
    for (int c0 = 0; c0 < NC; c0 += 16) {
        float4 a4 = *(const float4*)(W + (o0 + am) * NC + c0 + ak);
        sA[ak+0][am] = a4.x; sA[ak+1][am] = a4.y;
        sA[ak+2][am] = a4.z; sA[ak+3][am] = a4.w;
        *(float4*)&sB[bk2][bj] = *(const float4*)(xb + (c0 + bk2) * NL + l0 + bj);
        __syncthreads();
        #pragma unroll
        for (int k = 0; k < 16; k++) {
            float4 av = *(const float4*)&sA[k][m0];
            float4 bv = *(const float4*)&sB[k][j0];
            acc[0][0] += av.x*bv.x; acc[0][1] += av.x*bv.y; acc[0][2] += av.x*bv.z; acc[0][3] += av.x*bv.w;
            acc[1][0] += av.y*bv.x; acc[1][1] += av.y*bv.y; acc[1][2] += av.y*bv.z; acc[1][3] += av.y*bv.w;
            acc[2][0] += av.z*bv.x; acc[2][1] += av.z*bv.y; acc[2][2] += av.z*bv.z; acc[2][3] += av.z*bv.w;
            acc[3][0] += av.w*bv.x; acc[3][1] += av.w*bv.y; acc[3][2] += av.w*bv.z; acc[3][3] += av.w*bv.w;
        }
        __syncthreads();
    }

    float* yb = g_y + (size_t)b * NC * NL;
    #pragma unroll
    for (int i = 0; i < 4; i++) {
        int o = o0 + m0 + i;
        float bv = bias[o];
        float s1 = 0.f, s2 = 0.f;
        #pragma unroll
        for (int j = 0; j < 4; j++) {
            float v = acc[i][j] + bv;
            yb[(size_t)o * NL + l0 + j0 + j] = v;
            s1 += v; s2 += v * v;
        }
        // reduce across the 16 tx lanes (xor <= 8 stays within each 16-lane half)
        #pragma unroll
        for (int off = 8; off; off >>= 1) {
            s1 += __shfl_xor_sync(0xffffffffu, s1, off);
            s2 += __shfl_xor_sync(0xffffffffu, s2, off);
        }
        if (tx == 0) {
            atomicAdd(&g_sum[o],   s1);
            atomicAdd(&g_sumsq[o], s2);
        }
    }
}

// ---------------- kernel 4: BN finalize + ReLU + scale ----------------
__global__ void __launch_bounds__(256) k_bn(
    const float* __restrict__ gamma, const float* __restrict__ beta,
    const float* __restrict__ scale, float* __restrict__ out)
{
    int idx = blockIdx.x * 256 + threadIdx.x;
    if (idx >= NB*NC*NL) return;
    int ch = (idx / NL) & (NC - 1);
    const float invN = 1.f / (float)(NB * NL);
    float mean = g_sum[ch] * invN;
    float var  = g_sumsq[ch] * invN - mean * mean;
    float v = (g_y[idx] - mean) * rsqrtf(var + 1e-5f) * gamma[ch] + beta[ch];
    out[idx] = fmaxf(v, 0.f) * scale[ch];
}

// ---------------- launch ----------------
extern "C" void kernel_launch(void* const* d_in, const int* in_sizes, int n_in,
                              void* d_out, int out_size)
{
    const float* x     = (const float*)d_in[0];
    const float* Wc    = (const float*)d_in[1];
    const float* bc    = (const float*)d_in[2];
    const float* Wq    = (const float*)d_in[3];
    const float* bq    = (const float*)d_in[4];
    const float* Wk    = (const float*)d_in[5];
    const float* bk    = (const float*)d_in[6];
    const float* emb   = (const float*)d_in[7];
    const float* Wf    = (const float*)d_in[8];
    const float* bf    = (const float*)d_in[9];
    const float* gamma = (const float*)d_in[10];
    const float* beta  = (const float*)d_in[11];
    const float* scale = (const float*)d_in[12];
    float* out = (float*)d_out;

    const int SMEM_ATTN = (TT*65 + SW*65 + TT*(SW+1) + NREL*65) * (int)sizeof(float);
    cudaFuncSetAttribute(k_attn, cudaFuncAttributeMaxDynamicSharedMemorySize, SMEM_ATTN);

    k_zero<<<1, 256>>>();

    dim3 gP(NL/64, 12, NB);
    k_proj3<<<gP, 256>>>(Wc, bc, Wq, bq, Wk, bk, x);

    dim3 gA(NL/TT, NH, NB);
    k_attn<<<gA, 256, SMEM_ATTN>>>(emb);

    dim3 gG(NL/64, NC/64, NB);
    k_final<<<gG, 256>>>(Wf, bf);

    int total = NB*NC*NL;
    k_bn<<<(total + 255)/256, 256>>>(gamma, beta, scale, out);
}